// round 6
// baseline (speedup 1.0000x reference)
#include <cuda_runtime.h>
#include <cstdint>
#include <cstddef>

#define NN   1024
#define DIMX 384
#define HN   8
#define PDW  128
#define OUTW 1152   // H*DV + H*PD = 128 + 1024

static constexpr float SCALAR_SCALE = 0.14433756729740643f; // (3*16)^-0.5
static constexpr float PAIR_SCALE   = 0.5773502691896258f;  // 3^-0.5

// Scratch (static __device__ — no allocations allowed)
static __device__ float g_q[NN * 128];
static __device__ float g_k[NN * 128];
static __device__ float g_v[NN * 128];
static __device__ float g_S[(size_t)NN * NN * 8];  // 32 MB: logits, then overwritten with P=exp(logits)

typedef unsigned long long u64;

__device__ __forceinline__ u64 pack2(float lo, float hi) {
    u64 r; asm("mov.b64 %0, {%1, %2};" : "=l"(r) : "f"(lo), "f"(hi)); return r;
}
__device__ __forceinline__ void unpack2(u64 v, float& lo, float& hi) {
    asm("mov.b64 {%0, %1}, %2;" : "=f"(lo), "=f"(hi) : "l"(v));
}
__device__ __forceinline__ u64 ffma2(u64 a, u64 b, u64 c) {
    u64 r; asm("fma.rn.f32x2 %0, %1, %2, %3;" : "=l"(r) : "l"(a), "l"(b), "l"(c)); return r;
}
__device__ __forceinline__ u64 fmul2(u64 a, u64 b) {
    u64 r; asm("mul.rn.f32x2 %0, %1, %2;" : "=l"(r) : "l"(a), "l"(b)); return r;
}

// ---------------------------------------------------------------------------
// Kernel A: q/k/v projections. grid (32, 3), block 256 (8 warps).
// Block = 32 rows; warp = 4 rows; lane owns 4 cols. W L2 traffic amortized
// over 4 rows/warp: 768 warps x 196KB = 150 MB (was 600 MB).
// ---------------------------------------------------------------------------
__global__ void __launch_bounds__(256) proj_kernel(
    const float* __restrict__ x,
    const float* __restrict__ Wq,
    const float* __restrict__ Wk,
    const float* __restrict__ Wv)
{
    __shared__ float xs[32 * DIMX];   // 48 KB
    const int rb = blockIdx.x * 32;
    const float* W   = (blockIdx.y == 0) ? Wq  : (blockIdx.y == 1) ? Wk  : Wv;
    float*       dst = (blockIdx.y == 0) ? g_q : (blockIdx.y == 1) ? g_k : g_v;
    const float scale = (blockIdx.y == 0) ? SCALAR_SCALE : 1.0f;

    for (int t = threadIdx.x; t < 32 * DIMX; t += 256)
        xs[t] = x[(size_t)rb * DIMX + t];
    __syncthreads();

    const int wid  = threadIdx.x >> 5;
    const int lane = threadIdx.x & 31;
    const int c4   = lane * 4;
    const int r0   = wid * 4;

    float4 acc[4];
#pragma unroll
    for (int r = 0; r < 4; r++) acc[r] = make_float4(0.f, 0.f, 0.f, 0.f);

#pragma unroll 4
    for (int k = 0; k < DIMX; k++) {
        const float4 w = __ldg((const float4*)&W[k * 128 + c4]);
#pragma unroll
        for (int r = 0; r < 4; r++) {
            const float xv = xs[(r0 + r) * DIMX + k];
            acc[r].x = fmaf(xv, w.x, acc[r].x);
            acc[r].y = fmaf(xv, w.y, acc[r].y);
            acc[r].z = fmaf(xv, w.z, acc[r].z);
            acc[r].w = fmaf(xv, w.w, acc[r].w);
        }
    }
#pragma unroll
    for (int r = 0; r < 4; r++) {
        float4 o = acc[r];
        o.x *= scale; o.y *= scale; o.z *= scale; o.w *= scale;
        *(float4*)&dst[(size_t)(rb + r0 + r) * 128 + c4] = o;
    }
}

// ---------------------------------------------------------------------------
// Kernel B: S[i][j][h] = (q_i . k_j) + bb[h]*PAIR_SCALE.  grid 128, block 256.
// 8 warps = 8 query rows. k staged in smem 64-row chunks. Lane = (j4, h).
// ---------------------------------------------------------------------------
__global__ void __launch_bounds__(256) qk_kernel(const float* __restrict__ bb)
{
    __shared__ float ks[64 * 128];   // 32 KB

    const int wid  = threadIdx.x >> 5;
    const int lane = threadIdx.x & 31;
    const int i    = blockIdx.x * 8 + wid;
    const int j4   = lane >> 3;
    const int h    = lane & 7;

    const float4* qp = (const float4*)&g_q[(size_t)i * 128 + h * 16];
    const float4 q0 = qp[0], q1 = qp[1], q2 = qp[2], q3 = qp[3];
    const float bbh = bb[h] * PAIR_SCALE;

    for (int jc = 0; jc < NN; jc += 64) {
        __syncthreads();
#pragma unroll
        for (int u = 0; u < 8; u++)
            ((float4*)ks)[u * 256 + threadIdx.x] =
                ((const float4*)&g_k[(size_t)jc * 128])[u * 256 + threadIdx.x];
        __syncthreads();

        for (int jl = j4; jl < 64; jl += 4) {
            const float4* kp = (const float4*)&ks[jl * 128 + h * 16];
            const float4 k0 = kp[0], k1 = kp[1], k2 = kp[2], k3 = kp[3];
            float acc = q0.x * k0.x;
            acc = fmaf(q0.y, k0.y, acc); acc = fmaf(q0.z, k0.z, acc); acc = fmaf(q0.w, k0.w, acc);
            acc = fmaf(q1.x, k1.x, acc); acc = fmaf(q1.y, k1.y, acc);
            acc = fmaf(q1.z, k1.z, acc); acc = fmaf(q1.w, k1.w, acc);
            acc = fmaf(q2.x, k2.x, acc); acc = fmaf(q2.y, k2.y, acc);
            acc = fmaf(q2.z, k2.z, acc); acc = fmaf(q2.w, k2.w, acc);
            acc = fmaf(q3.x, k3.x, acc); acc = fmaf(q3.y, k3.y, acc);
            acc = fmaf(q3.z, k3.z, acc); acc = fmaf(q3.w, k3.w, acc);
            g_S[((size_t)i * NN + jc + jl) * 8 + h] = acc + bbh;
        }
    }
}

// ---------------------------------------------------------------------------
// Kernel C: bias + exp. Streams pairwise once; overwrites g_S with
// P = exp(S + (pr . Wb)*PAIR_SCALE) (unnormalized attention weights).
// grid 2048, block 256 (8 warps, no smem). Warp handles 64 consecutive rows.
// Lane = (h = lane&7, q = lane>>3). Lane's d-set: float4 chunks f = u*4+q,
// u = 0..7 — each LDG.128 instruction covers 64B CONTIGUOUS (1 L1 wavefront,
// broadcast x8 across heads). No accumulators -> ~84 regs, no spill.
// ---------------------------------------------------------------------------
__global__ void __launch_bounds__(256) bias_kernel(
    const float* __restrict__ pair,
    const float* __restrict__ Wb)
{
    const int tid  = threadIdx.x;
    const int wid  = tid >> 5;
    const int lane = tid & 31;
    const int h    = lane & 7;
    const int q    = lane >> 3;

    const int wg = blockIdx.x * 8 + wid;        // 0..16383
    const int i  = wg >> 4;
    const int j0 = (wg & 15) * 64;

    // Wb rows for this lane's d-set (chunks f = u*4+q), pre-scaled by PAIR_SCALE.
    u64 wb2[16];
#pragma unroll
    for (int u = 0; u < 8; u++) {
        const int d = (u * 4 + q) * 4;
        wb2[2 * u]     = pack2(Wb[(d + 0) * 8 + h] * PAIR_SCALE, Wb[(d + 1) * 8 + h] * PAIR_SCALE);
        wb2[2 * u + 1] = pack2(Wb[(d + 2) * 8 + h] * PAIR_SCALE, Wb[(d + 3) * 8 + h] * PAIR_SCALE);
    }

    const float4* pr4g = (const float4*)pair;

    for (int t = 0; t < 64; t++) {
        const size_t b = (size_t)i * NN + j0 + t;

        // front-batched: 8 x LDG.128 (each 64B contiguous across q-lanes) + LDG.32
        float4 pr4[8];
#pragma unroll
        for (int u = 0; u < 8; u++)
            pr4[u] = __ldg(pr4g + b * 32 + u * 4 + q);
        const float s = __ldg(g_S + b * 8 + h);

        u64 pr2[16];
#pragma unroll
        for (int u = 0; u < 8; u++) {
            pr2[2 * u]     = pack2(pr4[u].x, pr4[u].y);
            pr2[2 * u + 1] = pack2(pr4[u].z, pr4[u].w);
        }

        // two independent f32x2 chains
        u64 a0 = fmul2(pr2[0], wb2[0]);
        u64 a1 = fmul2(pr2[1], wb2[1]);
#pragma unroll
        for (int u = 1; u < 8; u++) {
            a0 = ffma2(pr2[2 * u],     wb2[2 * u],     a0);
            a1 = ffma2(pr2[2 * u + 1], wb2[2 * u + 1], a1);
        }
        float l0, h0, l1, h1;
        unpack2(a0, l0, h0); unpack2(a1, l1, h1);
        float dot = (l0 + h0) + (l1 + h1);
        dot += __shfl_xor_sync(0xffffffffu, dot, 8);
        dot += __shfl_xor_sync(0xffffffffu, dot, 16);

        const float p = __expf(dot + s);
        if (lane < 8)                      // q == 0 lanes store 8 heads, 32B
            g_S[b * 8 + h] = p;
    }
}

// ---------------------------------------------------------------------------
// Kernel D: dual aggregation + normalize. Streams pairwise (2nd time) and P.
// grid 128, block 512 (16 warps): warp -> (i = blk*8 + (wid&7), jpar = wid>>3).
// Lane owns d-slice [lane*4, lane*4+4). Per j: 1 LDG.128 pr + 2 broadcast
// LDG.128 P + 16 f32x2 FMA + 4 FMA + 8 FADD. NO shfl, NO exp. ~75 regs.
// ---------------------------------------------------------------------------
__global__ void __launch_bounds__(512, 1) attn_kernel(
    const float* __restrict__ pair,
    float* __restrict__ out)
{
    extern __shared__ float sm[];
    float* vs = sm;                  // 128 x 128 v-chunk (64 KB)
    float* mb = sm + 128 * 128;      // 8 x 1160 merge buffer (37 KB)

    const int tid  = threadIdx.x;
    const int wid  = tid >> 5;
    const int lane = tid & 31;
    const int iw   = wid & 7;
    const int jpar = wid >> 3;
    const int i    = blockIdx.x * 8 + iw;
    const bool lanehi = (lane >= 16);

    u64 accp[16];
#pragma unroll
    for (int t = 0; t < 16; t++) accp[t] = 0ull;
    float4 accv = make_float4(0.f, 0.f, 0.f, 0.f);
    float4 l03 = make_float4(0.f, 0.f, 0.f, 0.f);
    float4 l47 = make_float4(0.f, 0.f, 0.f, 0.f);

    const float4* gv4 = (const float4*)g_v;
    const float4* gp4 = (const float4*)g_S;     // P rows, 2 float4 per (i,j)
    const size_t irow = (size_t)i * NN;

    for (int jc = 0; jc < NN; jc += 128) {
        __syncthreads();
#pragma unroll
        for (int u = 0; u < 8; u++)
            ((float4*)vs)[u * 512 + tid] = gv4[(size_t)jc * 32 + u * 512 + tid];
        __syncthreads();

#pragma unroll 1
        for (int jl = jpar; jl < 128; jl += 2) {
            const size_t b = irow + jc + jl;

            const float4 pr  = __ldg((const float4*)pair + b * 32 + lane);
            const float4 p03 = __ldg(gp4 + b * 2);
            const float4 p47 = __ldg(gp4 + b * 2 + 1);

            l03.x += p03.x; l03.y += p03.y; l03.z += p03.z; l03.w += p03.w;
            l47.x += p47.x; l47.y += p47.y; l47.z += p47.z; l47.w += p47.w;

            const u64 pr01 = pack2(pr.x, pr.y);
            const u64 pr23 = pack2(pr.z, pr.w);
            const float p[8] = { p03.x, p03.y, p03.z, p03.w, p47.x, p47.y, p47.z, p47.w };

#pragma unroll
            for (int h = 0; h < 8; h++) {
                const u64 ph = pack2(p[h], p[h]);
                accp[2 * h]     = ffma2(ph, pr01, accp[2 * h]);
                accp[2 * h + 1] = ffma2(ph, pr23, accp[2 * h + 1]);
            }

#pragma unroll
            for (int r = 0; r < 4; r++) {
                const float pv = lanehi ? p[2 * r + 1] : p[2 * r];
                accv_set:;
                const float vv = vs[jl * 128 + r * 32 + lane];
                ((float*)&accv)[r] = fmaf(pv, vv, ((float*)&accv)[r]);
            }
        }
    }

    __syncthreads();

    // parity-1 warps dump partials
    if (jpar == 1) {
        float* m = mb + iw * 1160;
#pragma unroll
        for (int r = 0; r < 4; r++) m[r * 32 + lane] = ((float*)&accv)[r];
#pragma unroll
        for (int h = 0; h < 8; h++) {
            float a0, a1, a2, a3;
            unpack2(accp[2 * h],     a0, a1);
            unpack2(accp[2 * h + 1], a2, a3);
            *(float4*)&m[128 + h * 128 + lane * 4] = make_float4(a0, a1, a2, a3);
        }
        if (lane == 0) {
            *(float4*)&m[1152] = l03;
            *(float4*)&m[1156] = l47;
        }
    }
    __syncthreads();

    // parity-0 warps combine + normalize + store
    if (jpar == 0) {
        const float* m = mb + iw * 1160;
        const float4 ml03 = *(const float4*)&m[1152];
        const float4 ml47 = *(const float4*)&m[1156];
        float rinv[8];
        rinv[0] = 1.0f / (l03.x + ml03.x); rinv[1] = 1.0f / (l03.y + ml03.y);
        rinv[2] = 1.0f / (l03.z + ml03.z); rinv[3] = 1.0f / (l03.w + ml03.w);
        rinv[4] = 1.0f / (l47.x + ml47.x); rinv[5] = 1.0f / (l47.y + ml47.y);
        rinv[6] = 1.0f / (l47.z + ml47.z); rinv[7] = 1.0f / (l47.w + ml47.w);

        const size_t ob = (size_t)i * OUTW;
#pragma unroll
        for (int r = 0; r < 4; r++) {
            const float s = ((float*)&accv)[r] + m[r * 32 + lane];
            const float rv = lanehi ? rinv[2 * r + 1] : rinv[2 * r];
            out[ob + r * 32 + lane] = s * rv;
        }
#pragma unroll
        for (int h = 0; h < 8; h++) {
            float a0, a1, a2, a3;
            unpack2(accp[2 * h],     a0, a1);
            unpack2(accp[2 * h + 1], a2, a3);
            const float4 pm = *(const float4*)&m[128 + h * 128 + lane * 4];
            *(float4*)&out[ob + 128 + h * 128 + lane * 4] = make_float4(
                (a0 + pm.x) * rinv[h], (a1 + pm.y) * rinv[h],
                (a2 + pm.z) * rinv[h], (a3 + pm.w) * rinv[h]);
        }
    }
}

// ---------------------------------------------------------------------------
extern "C" void kernel_launch(void* const* d_in, const int* in_sizes, int n_in,
                              void* d_out, int out_size)
{
    (void)in_sizes; (void)n_in; (void)out_size;
    const float* x    = (const float*)d_in[0];
    const float* pair = (const float*)d_in[1];
    // d_in[2]=rotations, d_in[3]=translations, d_in[4]=mask: unused by reference math
    const float* Wq = (const float*)d_in[5];
    const float* Wk = (const float*)d_in[6];
    const float* Wv = (const float*)d_in[7];
    const float* Wb = (const float*)d_in[8];
    const float* bb = (const float*)d_in[9];
    float* out = (float*)d_out;

    proj_kernel<<<dim3(32, 3, 1), 256>>>(x, Wq, Wk, Wv);
    qk_kernel<<<128, 256>>>(bb);
    bias_kernel<<<2048, 256>>>(pair, Wb);

    const int smem = (128 * 128 + 8 * 1160) * (int)sizeof(float); // 102656 B
    cudaFuncSetAttribute(attn_kernel, cudaFuncAttributeMaxDynamicSharedMemorySize, smem);
    attn_kernel<<<128, 512, smem>>>(pair, out);
}

// round 7
// speedup vs baseline: 1.5007x; 1.5007x over previous
#include <cuda_runtime.h>
#include <cstdint>
#include <cstddef>

#define NN   1024
#define DIMX 384
#define HN   8
#define PDW  128
#define OUTW 1152   // H*DV + H*PD = 128 + 1024

static constexpr float SCALAR_SCALE = 0.14433756729740643f; // (3*16)^-0.5
static constexpr float PAIR_SCALE   = 0.5773502691896258f;  // 3^-0.5

// Scratch (static __device__ — no allocations allowed)
static __device__ float g_q[NN * 128];
static __device__ float g_k[NN * 128];
static __device__ float g_v[NN * 128];
static __device__ float g_S[(size_t)NN * NN * 8];  // 32 MB: logits, then P=exp(logits)

typedef unsigned long long u64;

__device__ __forceinline__ u64 pack2(float lo, float hi) {
    u64 r; asm("mov.b64 %0, {%1, %2};" : "=l"(r) : "f"(lo), "f"(hi)); return r;
}
__device__ __forceinline__ void unpack2(u64 v, float& lo, float& hi) {
    asm("mov.b64 {%0, %1}, %2;" : "=f"(lo), "=f"(hi) : "l"(v));
}
__device__ __forceinline__ u64 ffma2(u64 a, u64 b, u64 c) {
    u64 r; asm("fma.rn.f32x2 %0, %1, %2, %3;" : "=l"(r) : "l"(a), "l"(b), "l"(c)); return r;
}
__device__ __forceinline__ u64 fmul2(u64 a, u64 b) {
    u64 r; asm("mul.rn.f32x2 %0, %1, %2;" : "=l"(r) : "l"(a), "l"(b)); return r;
}

// ---------------------------------------------------------------------------
// Kernel A: q/k/v projections. grid (128, 3), block 256 (8 warps).
// Warp = one output row; lane owns 4 cols. 4-deep pipelined W loads (MLP=4).
// ---------------------------------------------------------------------------
__global__ void __launch_bounds__(256) proj_kernel(
    const float* __restrict__ x,
    const float* __restrict__ Wq,
    const float* __restrict__ Wk,
    const float* __restrict__ Wv)
{
    __shared__ float xs[8 * DIMX];
    const int rb = blockIdx.x * 8;
    const float* W   = (blockIdx.y == 0) ? Wq  : (blockIdx.y == 1) ? Wk  : Wv;
    float*       dst = (blockIdx.y == 0) ? g_q : (blockIdx.y == 1) ? g_k : g_v;
    const float scale = (blockIdx.y == 0) ? SCALAR_SCALE : 1.0f;

    for (int t = threadIdx.x; t < 8 * DIMX; t += 256)
        xs[t] = x[(size_t)rb * DIMX + t];
    __syncthreads();

    const int wid  = threadIdx.x >> 5;
    const int lane = threadIdx.x & 31;
    const int c4   = lane * 4;
    const float* xr = &xs[wid * DIMX];

    float4 wb[4];
#pragma unroll
    for (int u = 0; u < 4; u++)
        wb[u] = __ldg((const float4*)&W[u * 128 + c4]);

    float4 acc = make_float4(0.f, 0.f, 0.f, 0.f);
#pragma unroll 1
    for (int k0 = 0; k0 < DIMX; k0 += 4) {
#pragma unroll
        for (int u = 0; u < 4; u++) {
            const float4 w = wb[u];
            int kn = k0 + 4 + u;
            kn = (kn < DIMX) ? kn : u;               // clamp: keep address valid
            wb[u] = __ldg((const float4*)&W[kn * 128 + c4]);
            const float xv = xr[k0 + u];
            acc.x = fmaf(xv, w.x, acc.x);
            acc.y = fmaf(xv, w.y, acc.y);
            acc.z = fmaf(xv, w.z, acc.z);
            acc.w = fmaf(xv, w.w, acc.w);
        }
    }
    acc.x *= scale; acc.y *= scale; acc.z *= scale; acc.w *= scale;
    *(float4*)&dst[(size_t)(rb + wid) * 128 + c4] = acc;
}

// ---------------------------------------------------------------------------
// Kernel B: S[i][j][h] = (q_i . k_j) + bb[h]*PAIR_SCALE.
// grid 256 (i-oct x j-half), block 256 (8 warps = 8 query rows).
// k staged in smem 64-row chunks. Lane = (j4, h). Dot = 4 independent chains.
// ---------------------------------------------------------------------------
__global__ void __launch_bounds__(256) qk_kernel(const float* __restrict__ bb)
{
    __shared__ float ks[64 * 128];   // 32 KB

    const int wid  = threadIdx.x >> 5;
    const int lane = threadIdx.x & 31;
    const int i    = (blockIdx.x >> 1) * 8 + wid;
    const int jh0  = (blockIdx.x & 1) * 512;
    const int j4   = lane >> 3;
    const int h    = lane & 7;

    const float4* qp = (const float4*)&g_q[(size_t)i * 128 + h * 16];
    const float4 q0 = qp[0], q1 = qp[1], q2 = qp[2], q3 = qp[3];
    const float bbh = bb[h] * PAIR_SCALE;

    for (int jc = jh0; jc < jh0 + 512; jc += 64) {
        __syncthreads();
#pragma unroll
        for (int u = 0; u < 8; u++)
            ((float4*)ks)[u * 256 + threadIdx.x] =
                ((const float4*)&g_k[(size_t)jc * 128])[u * 256 + threadIdx.x];
        __syncthreads();

#pragma unroll 2
        for (int jl = j4; jl < 64; jl += 4) {
            const float4* kp = (const float4*)&ks[jl * 128 + h * 16];
            const float4 k0 = kp[0], k1 = kp[1], k2 = kp[2], k3 = kp[3];
            float a0 = q0.x * k0.x, a1 = q1.x * k1.x, a2 = q2.x * k2.x, a3 = q3.x * k3.x;
            a0 = fmaf(q0.y, k0.y, a0); a1 = fmaf(q1.y, k1.y, a1);
            a2 = fmaf(q2.y, k2.y, a2); a3 = fmaf(q3.y, k3.y, a3);
            a0 = fmaf(q0.z, k0.z, a0); a1 = fmaf(q1.z, k1.z, a1);
            a2 = fmaf(q2.z, k2.z, a2); a3 = fmaf(q3.z, k3.z, a3);
            a0 = fmaf(q0.w, k0.w, a0); a1 = fmaf(q1.w, k1.w, a1);
            a2 = fmaf(q2.w, k2.w, a2); a3 = fmaf(q3.w, k3.w, a3);
            g_S[((size_t)i * NN + jc + jl) * 8 + h] = ((a0 + a1) + (a2 + a3)) + bbh;
        }
    }
}

// ---------------------------------------------------------------------------
// Kernel C: bias + exp -> overwrite g_S with P = exp(S + (pr.Wb)*PAIR_SCALE).
// grid 2048, block 256 (8 warps). Warp = 64 consecutive j of one i row.
// Lane = (h = lane&7, q = lane>>3); d-chunks f = u*4+q (contiguous LDG.128).
// Rolling 1-ahead prefetch of the next row's 8 x LDG.128 + LDG.32.
// ---------------------------------------------------------------------------
__global__ void __launch_bounds__(256, 2) bias_kernel(
    const float* __restrict__ pair,
    const float* __restrict__ Wb)
{
    const int tid  = threadIdx.x;
    const int wid  = tid >> 5;
    const int lane = tid & 31;
    const int h    = lane & 7;
    const int q    = lane >> 3;

    const int wg = blockIdx.x * 8 + wid;        // 0..16383
    const int i  = wg >> 4;
    const int j0 = (wg & 15) * 64;
    const size_t base0 = (size_t)i * NN + j0;

    u64 wb2[16];
#pragma unroll
    for (int u = 0; u < 8; u++) {
        const int d = (u * 4 + q) * 4;
        wb2[2 * u]     = pack2(Wb[(d + 0) * 8 + h] * PAIR_SCALE, Wb[(d + 1) * 8 + h] * PAIR_SCALE);
        wb2[2 * u + 1] = pack2(Wb[(d + 2) * 8 + h] * PAIR_SCALE, Wb[(d + 3) * 8 + h] * PAIR_SCALE);
    }

    const float4* pr4g = (const float4*)pair;

    // prefetch stage (next row)
    float4 prn[8];
    float  sn;
#pragma unroll
    for (int u = 0; u < 8; u++) prn[u] = __ldg(pr4g + base0 * 32 + u * 4 + q);
    sn = __ldg(g_S + base0 * 8 + h);

#pragma unroll 2
    for (int t = 0; t < 64; t++) {
        float4 prc[8];
#pragma unroll
        for (int u = 0; u < 8; u++) prc[u] = prn[u];
        const float sc = sn;

        const int tn = (t + 1 < 64) ? (t + 1) : 0;       // clamp: valid addr
        const size_t bn = base0 + tn;
#pragma unroll
        for (int u = 0; u < 8; u++) prn[u] = __ldg(pr4g + bn * 32 + u * 4 + q);
        sn = __ldg(g_S + bn * 8 + h);

        u64 pr2[16];
#pragma unroll
        for (int u = 0; u < 8; u++) {
            pr2[2 * u]     = pack2(prc[u].x, prc[u].y);
            pr2[2 * u + 1] = pack2(prc[u].z, prc[u].w);
        }
        u64 a0 = fmul2(pr2[0], wb2[0]);
        u64 a1 = fmul2(pr2[1], wb2[1]);
#pragma unroll
        for (int u = 1; u < 8; u++) {
            a0 = ffma2(pr2[2 * u],     wb2[2 * u],     a0);
            a1 = ffma2(pr2[2 * u + 1], wb2[2 * u + 1], a1);
        }
        float l0, h0, l1, h1;
        unpack2(a0, l0, h0); unpack2(a1, l1, h1);
        float dot = (l0 + h0) + (l1 + h1);
        dot += __shfl_xor_sync(0xffffffffu, dot, 8);
        dot += __shfl_xor_sync(0xffffffffu, dot, 16);

        const float p = __expf(dot + sc);
        if (lane < 8)
            g_S[(base0 + t) * 8 + h] = p;
    }
}

// ---------------------------------------------------------------------------
// Kernel D: dual aggregation + normalize. Streams pairwise + P.
// grid 128, block 512 (16 warps): warp -> (i = blk*8 + (wid&7), jpar = wid>>3).
// Lane owns d-slice [lane*4, lane*4+4). 2-deep rolling prefetch of (pr, P),
// wrapping across v-chunk boundaries: (jc+jl+2)&1023 is the warp's next j.
// NO shfl, NO exp in the loop.
// ---------------------------------------------------------------------------
__global__ void __launch_bounds__(512, 1) attn_kernel(
    const float* __restrict__ pair,
    float* __restrict__ out)
{
    extern __shared__ float sm[];
    float* vs = sm;                  // 128 x 128 v-chunk (64 KB)
    float* mb = sm + 128 * 128;      // 8 x 1160 merge buffer (37 KB)

    const int tid  = threadIdx.x;
    const int wid  = tid >> 5;
    const int lane = tid & 31;
    const int iw   = wid & 7;
    const int jpar = wid >> 3;
    const int i    = blockIdx.x * 8 + iw;
    const bool lanehi = (lane >= 16);

    u64 accp[16];
#pragma unroll
    for (int t = 0; t < 16; t++) accp[t] = 0ull;
    float accv[4] = {0.f, 0.f, 0.f, 0.f};
    float4 l03 = make_float4(0.f, 0.f, 0.f, 0.f);
    float4 l47 = make_float4(0.f, 0.f, 0.f, 0.f);

    const float4* gv4 = (const float4*)g_v;
    const float4* gp4 = (const float4*)g_S;     // P rows, 2 float4 per (i,j)
    const float4* pp4 = (const float4*)pair;
    const size_t irow = (size_t)i * NN;

    // 2-deep prefetch stages: N1 = j, N2 = j+2 (warp stride 2)
    float4 prN1, pN1a, pN1b, prN2, pN2a, pN2b;
    {
        const size_t b1 = irow + jpar;
        const size_t b2 = irow + jpar + 2;
        prN1 = __ldg(pp4 + b1 * 32 + lane);
        pN1a = __ldg(gp4 + b1 * 2);  pN1b = __ldg(gp4 + b1 * 2 + 1);
        prN2 = __ldg(pp4 + b2 * 32 + lane);
        pN2a = __ldg(gp4 + b2 * 2);  pN2b = __ldg(gp4 + b2 * 2 + 1);
    }

    for (int jc = 0; jc < NN; jc += 128) {
        __syncthreads();
#pragma unroll
        for (int u = 0; u < 8; u++)
            ((float4*)vs)[u * 512 + tid] = gv4[(size_t)jc * 32 + u * 512 + tid];
        __syncthreads();

#pragma unroll 2
        for (int jl = jpar; jl < 128; jl += 2) {
            // consume stage N1, rotate N2 -> N1, load new N2 at j+4
            const float4 pr  = prN1;
            const float4 p03 = pN1a;
            const float4 p47 = pN1b;
            prN1 = prN2; pN1a = pN2a; pN1b = pN2b;

            const int jn = (jc + jl + 4) & (NN - 1);   // next-next j (wraps valid)
            const size_t bn = irow + jn;
            prN2 = __ldg(pp4 + bn * 32 + lane);
            pN2a = __ldg(gp4 + bn * 2);
            pN2b = __ldg(gp4 + bn * 2 + 1);

            l03.x += p03.x; l03.y += p03.y; l03.z += p03.z; l03.w += p03.w;
            l47.x += p47.x; l47.y += p47.y; l47.z += p47.z; l47.w += p47.w;

            const u64 pr01 = pack2(pr.x, pr.y);
            const u64 pr23 = pack2(pr.z, pr.w);
            const float p[8] = { p03.x, p03.y, p03.z, p03.w, p47.x, p47.y, p47.z, p47.w };

#pragma unroll
            for (int h = 0; h < 8; h++) {
                const u64 ph = pack2(p[h], p[h]);
                accp[2 * h]     = ffma2(ph, pr01, accp[2 * h]);
                accp[2 * h + 1] = ffma2(ph, pr23, accp[2 * h + 1]);
            }

#pragma unroll
            for (int r = 0; r < 4; r++) {
                const float pv = lanehi ? p[2 * r + 1] : p[2 * r];
                accv[r] = fmaf(pv, vs[jl * 128 + r * 32 + lane], accv[r]);
            }
        }
    }

    __syncthreads();

    // parity-1 warps dump partials
    if (jpar == 1) {
        float* m = mb + iw * 1160;
#pragma unroll
        for (int r = 0; r < 4; r++) m[r * 32 + lane] = accv[r];
#pragma unroll
        for (int h = 0; h < 8; h++) {
            float a0, a1, a2, a3;
            unpack2(accp[2 * h],     a0, a1);
            unpack2(accp[2 * h + 1], a2, a3);
            *(float4*)&m[128 + h * 128 + lane * 4] = make_float4(a0, a1, a2, a3);
        }
        if (lane == 0) {
            *(float4*)&m[1152] = l03;
            *(float4*)&m[1156] = l47;
        }
    }
    __syncthreads();

    // parity-0 warps combine + normalize + store
    if (jpar == 0) {
        const float* m = mb + iw * 1160;
        const float4 ml03 = *(const float4*)&m[1152];
        const float4 ml47 = *(const float4*)&m[1156];
        float rinv[8];
        rinv[0] = 1.0f / (l03.x + ml03.x); rinv[1] = 1.0f / (l03.y + ml03.y);
        rinv[2] = 1.0f / (l03.z + ml03.z); rinv[3] = 1.0f / (l03.w + ml03.w);
        rinv[4] = 1.0f / (l47.x + ml47.x); rinv[5] = 1.0f / (l47.y + ml47.y);
        rinv[6] = 1.0f / (l47.z + ml47.z); rinv[7] = 1.0f / (l47.w + ml47.w);

        const size_t ob = (size_t)i * OUTW;
#pragma unroll
        for (int r = 0; r < 4; r++) {
            const float s = accv[r] + m[r * 32 + lane];
            const float rv = lanehi ? rinv[2 * r + 1] : rinv[2 * r];
            out[ob + r * 32 + lane] = s * rv;
        }
#pragma unroll
        for (int h = 0; h < 8; h++) {
            float a0, a1, a2, a3;
            unpack2(accp[2 * h],     a0, a1);
            unpack2(accp[2 * h + 1], a2, a3);
            const float4 pm = *(const float4*)&m[128 + h * 128 + lane * 4];
            *(float4*)&out[ob + 128 + h * 128 + lane * 4] = make_float4(
                (a0 + pm.x) * rinv[h], (a1 + pm.y) * rinv[h],
                (a2 + pm.z) * rinv[h], (a3 + pm.w) * rinv[h]);
        }
    }
}

// ---------------------------------------------------------------------------
extern "C" void kernel_launch(void* const* d_in, const int* in_sizes, int n_in,
                              void* d_out, int out_size)
{
    (void)in_sizes; (void)n_in; (void)out_size;
    const float* x    = (const float*)d_in[0];
    const float* pair = (const float*)d_in[1];
    // d_in[2]=rotations, d_in[3]=translations, d_in[4]=mask: unused by reference math
    const float* Wq = (const float*)d_in[5];
    const float* Wk = (const float*)d_in[6];
    const float* Wv = (const float*)d_in[7];
    const float* Wb = (const float*)d_in[8];
    const float* bb = (const float*)d_in[9];
    float* out = (float*)d_out;

    proj_kernel<<<dim3(128, 3, 1), 256>>>(x, Wq, Wk, Wv);
    qk_kernel<<<256, 256>>>(bb);
    bias_kernel<<<2048, 256>>>(pair, Wb);

    const int smem = (128 * 128 + 8 * 1160) * (int)sizeof(float); // 102656 B
    cudaFuncSetAttribute(attn_kernel, cudaFuncAttributeMaxDynamicSharedMemorySize, smem);
    attn_kernel<<<128, 512, smem>>>(pair, out);
}

// round 8
// speedup vs baseline: 1.6486x; 1.0985x over previous
#include <cuda_runtime.h>
#include <cstdint>
#include <cstddef>

#define NN   1024
#define DIMX 384
#define HN   8
#define PDW  128
#define OUTW 1152   // H*DV + H*PD = 128 + 1024

static constexpr float SCALAR_SCALE = 0.14433756729740643f; // (3*16)^-0.5
static constexpr float PAIR_SCALE   = 0.5773502691896258f;  // 3^-0.5

// Scratch (static __device__ — no allocations allowed)
static __device__ float g_q[NN * 128];
static __device__ float g_k[NN * 128];
static __device__ float g_v[NN * 128];
static __device__ float g_P[(size_t)NN * NN * 8];      // 32 MB: P = exp(logits), [i][j][h]
static __device__ float g_part[(size_t)NN * 2 * 1184]; // 9.7 MB: per-(i,half) partials

typedef unsigned long long u64;

__device__ __forceinline__ u64 pack2(float lo, float hi) {
    u64 r; asm("mov.b64 %0, {%1, %2};" : "=l"(r) : "f"(lo), "f"(hi)); return r;
}
__device__ __forceinline__ void unpack2(u64 v, float& lo, float& hi) {
    asm("mov.b64 {%0, %1}, %2;" : "=f"(lo), "=f"(hi) : "l"(v));
}
__device__ __forceinline__ u64 ffma2(u64 a, u64 b, u64 c) {
    u64 r; asm("fma.rn.f32x2 %0, %1, %2, %3;" : "=l"(r) : "l"(a), "l"(b), "l"(c)); return r;
}
__device__ __forceinline__ u64 fmul2(u64 a, u64 b) {
    u64 r; asm("mul.rn.f32x2 %0, %1, %2;" : "=l"(r) : "l"(a), "l"(b)); return r;
}

// ---------------------------------------------------------------------------
// Kernel A: q/k/v projections. grid (128, 3), block 256 (8 warps).
// Warp = one output row; lane owns 4 cols. 4-deep pipelined W loads.
// ---------------------------------------------------------------------------
__global__ void __launch_bounds__(256) proj_kernel(
    const float* __restrict__ x,
    const float* __restrict__ Wq,
    const float* __restrict__ Wk,
    const float* __restrict__ Wv)
{
    __shared__ float xs[8 * DIMX];
    const int rb = blockIdx.x * 8;
    const float* W   = (blockIdx.y == 0) ? Wq  : (blockIdx.y == 1) ? Wk  : Wv;
    float*       dst = (blockIdx.y == 0) ? g_q : (blockIdx.y == 1) ? g_k : g_v;
    const float scale = (blockIdx.y == 0) ? SCALAR_SCALE : 1.0f;

    for (int t = threadIdx.x; t < 8 * DIMX; t += 256)
        xs[t] = x[(size_t)rb * DIMX + t];
    __syncthreads();

    const int wid  = threadIdx.x >> 5;
    const int lane = threadIdx.x & 31;
    const int c4   = lane * 4;
    const float* xr = &xs[wid * DIMX];

    float4 wb[4];
#pragma unroll
    for (int u = 0; u < 4; u++)
        wb[u] = __ldg((const float4*)&W[u * 128 + c4]);

    float4 acc = make_float4(0.f, 0.f, 0.f, 0.f);
#pragma unroll 1
    for (int k0 = 0; k0 < DIMX; k0 += 4) {
#pragma unroll
        for (int u = 0; u < 4; u++) {
            const float4 w = wb[u];
            int kn = k0 + 4 + u;
            kn = (kn < DIMX) ? kn : u;               // clamp: keep address valid
            wb[u] = __ldg((const float4*)&W[kn * 128 + c4]);
            const float xv = xr[k0 + u];
            acc.x = fmaf(xv, w.x, acc.x);
            acc.y = fmaf(xv, w.y, acc.y);
            acc.z = fmaf(xv, w.z, acc.z);
            acc.w = fmaf(xv, w.w, acc.w);
        }
    }
    acc.x *= scale; acc.y *= scale; acc.z *= scale; acc.w *= scale;
    *(float4*)&dst[(size_t)(rb + wid) * 128 + c4] = acc;
}

// ---------------------------------------------------------------------------
// Kernel B: FUSED qk + bias + exp -> g_P = exp(q.k + (pr.Wb + bb)*PAIR_SCALE).
// grid 2048, block 256 (8 warps, 2 CTAs/SM). Warp = 64 consecutive j of one i.
// Lane = (h = lane&7, q = lane>>3). Lane's pair d-chunks f = u*4+q (each
// LDG.128 is 64B contiguous across q-lanes). qk dot: lane covers q-quarter of
// head h's 16 dims (4 MACs, k row L2-resident, 1 LDG.128/j). The xor8/xor16
// fold reduces qk-partial + bias-partial simultaneously (same structure).
// Rolling 1-ahead prefetch of the next j's pair row + k row.
// ---------------------------------------------------------------------------
__global__ void __launch_bounds__(256, 2) qkbias_kernel(
    const float* __restrict__ pair,
    const float* __restrict__ Wb,
    const float* __restrict__ bb)
{
    const int tid  = threadIdx.x;
    const int wid  = tid >> 5;
    const int lane = tid & 31;
    const int h    = lane & 7;
    const int q    = lane >> 3;

    const int wg = blockIdx.x * 8 + wid;        // 0..16383
    const int i  = wg >> 4;
    const int j0 = (wg & 15) * 64;
    const size_t base0 = (size_t)i * NN + j0;

    // Wb rows for this lane's d-set, pre-scaled by PAIR_SCALE.
    u64 wb2[16];
#pragma unroll
    for (int u = 0; u < 8; u++) {
        const int d = (u * 4 + q) * 4;
        wb2[2 * u]     = pack2(Wb[(d + 0) * 8 + h] * PAIR_SCALE, Wb[(d + 1) * 8 + h] * PAIR_SCALE);
        wb2[2 * u + 1] = pack2(Wb[(d + 2) * 8 + h] * PAIR_SCALE, Wb[(d + 3) * 8 + h] * PAIR_SCALE);
    }
    // q slice for (h, quarter): 4 floats (q pre-scaled by SCALAR_SCALE in proj)
    const float4 qv = *(const float4*)&g_q[(size_t)i * 128 + h * 16 + q * 4];
    const float bbh = bb[h] * PAIR_SCALE;

    const float4* pr4g = (const float4*)pair;
    const float4* k4g  = (const float4*)g_k;
    const int koff = h * 4 + q;                 // float4 index of (h,q) slice in a 128-f row

    // prefetch stage
    float4 prn[8], kn;
#pragma unroll
    for (int u = 0; u < 8; u++) prn[u] = __ldg(pr4g + base0 * 32 + u * 4 + q);
    kn = __ldg(k4g + (size_t)(j0)*32 + koff);

#pragma unroll 2
    for (int t = 0; t < 64; t++) {
        float4 prc[8];
#pragma unroll
        for (int u = 0; u < 8; u++) prc[u] = prn[u];
        const float4 kc = kn;

        const int tn = (t + 1 < 64) ? (t + 1) : 0;       // clamp: valid addr
        const size_t bn = base0 + tn;
#pragma unroll
        for (int u = 0; u < 8; u++) prn[u] = __ldg(pr4g + bn * 32 + u * 4 + q);
        kn = __ldg(k4g + (size_t)(j0 + tn) * 32 + koff);

        u64 pr2[16];
#pragma unroll
        for (int u = 0; u < 8; u++) {
            pr2[2 * u]     = pack2(prc[u].x, prc[u].y);
            pr2[2 * u + 1] = pack2(prc[u].z, prc[u].w);
        }
        u64 a0 = fmul2(pr2[0], wb2[0]);
        u64 a1 = fmul2(pr2[1], wb2[1]);
#pragma unroll
        for (int u = 1; u < 8; u++) {
            a0 = ffma2(pr2[2 * u],     wb2[2 * u],     a0);
            a1 = ffma2(pr2[2 * u + 1], wb2[2 * u + 1], a1);
        }
        float l0, h0, l1, h1;
        unpack2(a0, l0, h0); unpack2(a1, l1, h1);

        // qk partial for (h, quarter): 4 MACs
        float qk = qv.x * kc.x;
        qk = fmaf(qv.y, kc.y, qk);
        qk = fmaf(qv.z, kc.z, qk);
        qk = fmaf(qv.w, kc.w, qk);

        float dot = ((l0 + h0) + (l1 + h1)) + qk;
        dot += __shfl_xor_sync(0xffffffffu, dot, 8);
        dot += __shfl_xor_sync(0xffffffffu, dot, 16);

        const float p = __expf(dot + bbh);
        if (lane < 8)
            g_P[(base0 + t) * 8 + h] = p;
    }
}

// ---------------------------------------------------------------------------
// Kernel C: dual aggregation (partials). grid 256: CTA -> (i-oct, j-half).
// block 512 (16 warps): warp -> (iw = wid&7, jpar = wid>>3); 256 j's each.
// Lane owns d-slice [lane*4, lane*4+4). 2-deep rolling prefetch of (pr, P).
// Writes UNNORMALIZED partials + denom to g_part[(i*2+half)*1184 + ...].
// ---------------------------------------------------------------------------
__global__ void __launch_bounds__(512, 1) attn_kernel(
    const float* __restrict__ pair)
{
    extern __shared__ float sm[];
    float* vs = sm;                  // 128 x 128 v-chunk (64 KB)
    float* mb = sm + 128 * 128;      // 8 x 1160 merge buffer (37 KB)

    const int tid  = threadIdx.x;
    const int wid  = tid >> 5;
    const int lane = tid & 31;
    const int iw   = wid & 7;
    const int jpar = wid >> 3;
    const int half = blockIdx.x & 1;
    const int i    = (blockIdx.x >> 1) * 8 + iw;
    const int jh0  = half * 512;
    const bool lanehi = (lane >= 16);

    u64 accp[16];
#pragma unroll
    for (int t = 0; t < 16; t++) accp[t] = 0ull;
    float accv[4] = {0.f, 0.f, 0.f, 0.f};
    float4 l03 = make_float4(0.f, 0.f, 0.f, 0.f);
    float4 l47 = make_float4(0.f, 0.f, 0.f, 0.f);

    const float4* gv4 = (const float4*)g_v;
    const float4* gp4 = (const float4*)g_P;     // P rows, 2 float4 per (i,j)
    const float4* pp4 = (const float4*)pair;
    const size_t irow = (size_t)i * NN;
    const int jmax = jh0 + 511;

    // 2-deep prefetch: N1 = j, N2 = j+2
    float4 prN1, pN1a, pN1b, prN2, pN2a, pN2b;
    {
        const size_t b1 = irow + jh0 + jpar;
        const size_t b2 = b1 + 2;
        prN1 = __ldg(pp4 + b1 * 32 + lane);
        pN1a = __ldg(gp4 + b1 * 2);  pN1b = __ldg(gp4 + b1 * 2 + 1);
        prN2 = __ldg(pp4 + b2 * 32 + lane);
        pN2a = __ldg(gp4 + b2 * 2);  pN2b = __ldg(gp4 + b2 * 2 + 1);
    }

    for (int jc = jh0; jc < jh0 + 512; jc += 128) {
        __syncthreads();
#pragma unroll
        for (int u = 0; u < 8; u++)
            ((float4*)vs)[u * 512 + tid] = gv4[(size_t)jc * 32 + u * 512 + tid];
        __syncthreads();

#pragma unroll 2
        for (int jl = jpar; jl < 128; jl += 2) {
            const float4 pr  = prN1;
            const float4 p03 = pN1a;
            const float4 p47 = pN1b;
            prN1 = prN2; pN1a = pN2a; pN1b = pN2b;

            int jn = jc + jl + 4;                      // next-next j
            jn = (jn <= jmax) ? jn : jmax;             // clamp: valid addr
            const size_t bn = irow + jn;
            prN2 = __ldg(pp4 + bn * 32 + lane);
            pN2a = __ldg(gp4 + bn * 2);
            pN2b = __ldg(gp4 + bn * 2 + 1);

            l03.x += p03.x; l03.y += p03.y; l03.z += p03.z; l03.w += p03.w;
            l47.x += p47.x; l47.y += p47.y; l47.z += p47.z; l47.w += p47.w;

            const u64 pr01 = pack2(pr.x, pr.y);
            const u64 pr23 = pack2(pr.z, pr.w);
            const float p[8] = { p03.x, p03.y, p03.z, p03.w, p47.x, p47.y, p47.z, p47.w };

#pragma unroll
            for (int h = 0; h < 8; h++) {
                const u64 ph = pack2(p[h], p[h]);
                accp[2 * h]     = ffma2(ph, pr01, accp[2 * h]);
                accp[2 * h + 1] = ffma2(ph, pr23, accp[2 * h + 1]);
            }

#pragma unroll
            for (int r = 0; r < 4; r++) {
                const float pv = lanehi ? p[2 * r + 1] : p[2 * r];
                accv[r] = fmaf(pv, vs[(jl + (jc - jh0) - (jc - jh0)) * 128 + r * 32 + lane], accv[r]);
            }
        }
    }

    __syncthreads();

    // parity-1 warps dump partials to smem
    if (jpar == 1) {
        float* m = mb + iw * 1160;
#pragma unroll
        for (int r = 0; r < 4; r++) m[r * 32 + lane] = accv[r];
#pragma unroll
        for (int h = 0; h < 8; h++) {
            float a0, a1, a2, a3;
            unpack2(accp[2 * h],     a0, a1);
            unpack2(accp[2 * h + 1], a2, a3);
            *(float4*)&m[128 + h * 128 + lane * 4] = make_float4(a0, a1, a2, a3);
        }
        if (lane == 0) {
            *(float4*)&m[1152] = l03;
            *(float4*)&m[1156] = l47;
        }
    }
    __syncthreads();

    // parity-0 warps combine and write UNNORMALIZED partials to global
    if (jpar == 0) {
        const float* m = mb + iw * 1160;
        float* gp = g_part + (size_t)(i * 2 + half) * 1184;

#pragma unroll
        for (int r = 0; r < 4; r++)
            gp[r * 32 + lane] = accv[r] + m[r * 32 + lane];
#pragma unroll
        for (int h = 0; h < 8; h++) {
            float a0, a1, a2, a3;
            unpack2(accp[2 * h],     a0, a1);
            unpack2(accp[2 * h + 1], a2, a3);
            const float4 pm = *(const float4*)&m[128 + h * 128 + lane * 4];
            *(float4*)&gp[128 + h * 128 + lane * 4] = make_float4(
                a0 + pm.x, a1 + pm.y, a2 + pm.z, a3 + pm.w);
        }
        if (lane == 0) {
            const float4 ml03 = *(const float4*)&m[1152];
            const float4 ml47 = *(const float4*)&m[1156];
            *(float4*)&gp[1152] = make_float4(l03.x + ml03.x, l03.y + ml03.y,
                                              l03.z + ml03.z, l03.w + ml03.w);
            *(float4*)&gp[1156] = make_float4(l47.x + ml47.x, l47.y + ml47.y,
                                              l47.z + ml47.z, l47.w + ml47.w);
        }
    }
}

// ---------------------------------------------------------------------------
// Kernel D: merge halves + normalize + store. grid 64, block 512.
// Warp = one query i.
// ---------------------------------------------------------------------------
__global__ void __launch_bounds__(512) merge_kernel(float* __restrict__ out)
{
    const int wid  = threadIdx.x >> 5;
    const int lane = threadIdx.x & 31;
    const int i    = blockIdx.x * 16 + wid;
    const bool lanehi = (lane >= 16);

    const float* pa = g_part + (size_t)(i * 2) * 1184;
    const float* pb = pa + 1184;

    float r_own = 0.0f;
    if (lane < 8)
        r_own = 1.0f / (pa[1152 + lane] + pb[1152 + lane]);
    float rinv[8];
#pragma unroll
    for (int h = 0; h < 8; h++)
        rinv[h] = __shfl_sync(0xffffffffu, r_own, h);

    const size_t ob = (size_t)i * OUTW;
#pragma unroll
    for (int r = 0; r < 4; r++) {
        const float s = pa[r * 32 + lane] + pb[r * 32 + lane];
        const float rv = lanehi ? rinv[2 * r + 1] : rinv[2 * r];
        out[ob + r * 32 + lane] = s * rv;
    }
#pragma unroll
    for (int h = 0; h < 8; h++) {
        const float4 a = *(const float4*)&pa[128 + h * 128 + lane * 4];
        const float4 b = *(const float4*)&pb[128 + h * 128 + lane * 4];
        *(float4*)&out[ob + 128 + h * 128 + lane * 4] = make_float4(
            (a.x + b.x) * rinv[h], (a.y + b.y) * rinv[h],
            (a.z + b.z) * rinv[h], (a.w + b.w) * rinv[h]);
    }
}

// ---------------------------------------------------------------------------
extern "C" void kernel_launch(void* const* d_in, const int* in_sizes, int n_in,
                              void* d_out, int out_size)
{
    (void)in_sizes; (void)n_in; (void)out_size;
    const float* x    = (const float*)d_in[0];
    const float* pair = (const float*)d_in[1];
    // d_in[2]=rotations, d_in[3]=translations, d_in[4]=mask: unused by reference math
    const float* Wq = (const float*)d_in[5];
    const float* Wk = (const float*)d_in[6];
    const float* Wv = (const float*)d_in[7];
    const float* Wb = (const float*)d_in[8];
    const float* bb = (const float*)d_in[9];
    float* out = (float*)d_out;

    proj_kernel<<<dim3(128, 3, 1), 256>>>(x, Wq, Wk, Wv);
    qkbias_kernel<<<2048, 256>>>(pair, Wb, bb);

    const int smem = (128 * 128 + 8 * 1160) * (int)sizeof(float); // 102656 B
    cudaFuncSetAttribute(attn_kernel, cudaFuncAttributeMaxDynamicSharedMemorySize, smem);
    attn_kernel<<<256, 512, smem>>>(pair);

    merge_kernel<<<64, 512>>>(out);
}

// round 9
// speedup vs baseline: 1.7557x; 1.0650x over previous
#include <cuda_runtime.h>
#include <cstdint>
#include <cstddef>

#define NN   1024
#define DIMX 384
#define HN   8
#define PDW  128
#define OUTW 1152   // H*DV + H*PD = 128 + 1024

static constexpr float SCALAR_SCALE = 0.14433756729740643f; // (3*16)^-0.5
static constexpr float PAIR_SCALE   = 0.5773502691896258f;  // 3^-0.5

// Scratch (static __device__ — no allocations allowed)
static __device__ float g_q[NN * 128];
static __device__ float g_k[NN * 128];
static __device__ float g_v[NN * 128];

typedef unsigned long long u64;

__device__ __forceinline__ u64 pack2(float lo, float hi) {
    u64 r; asm("mov.b64 %0, {%1, %2};" : "=l"(r) : "f"(lo), "f"(hi)); return r;
}
__device__ __forceinline__ void unpack2(u64 v, float& lo, float& hi) {
    asm("mov.b64 {%0, %1}, %2;" : "=f"(lo), "=f"(hi) : "l"(v));
}
__device__ __forceinline__ u64 ffma2(u64 a, u64 b, u64 c) {
    u64 r; asm("fma.rn.f32x2 %0, %1, %2, %3;" : "=l"(r) : "l"(a), "l"(b), "l"(c)); return r;
}
__device__ __forceinline__ u64 fmul2(u64 a, u64 b) {
    u64 r; asm("mul.rn.f32x2 %0, %1, %2;" : "=l"(r) : "l"(a), "l"(b)); return r;
}

// ---------------------------------------------------------------------------
// Kernel A: q/k/v projections. grid (128, 3), block 256 (8 warps).
// Warp = one output row; lane owns 4 cols. 4-deep pipelined W loads.
// ---------------------------------------------------------------------------
__global__ void __launch_bounds__(256) proj_kernel(
    const float* __restrict__ x,
    const float* __restrict__ Wq,
    const float* __restrict__ Wk,
    const float* __restrict__ Wv)
{
    __shared__ float xs[8 * DIMX];
    const int rb = blockIdx.x * 8;
    const float* W   = (blockIdx.y == 0) ? Wq  : (blockIdx.y == 1) ? Wk  : Wv;
    float*       dst = (blockIdx.y == 0) ? g_q : (blockIdx.y == 1) ? g_k : g_v;
    const float scale = (blockIdx.y == 0) ? SCALAR_SCALE : 1.0f;

    for (int t = threadIdx.x; t < 8 * DIMX; t += 256)
        xs[t] = x[(size_t)rb * DIMX + t];
    __syncthreads();

    const int wid  = threadIdx.x >> 5;
    const int lane = threadIdx.x & 31;
    const int c4   = lane * 4;
    const float* xr = &xs[wid * DIMX];

    float4 wb[4];
#pragma unroll
    for (int u = 0; u < 4; u++)
        wb[u] = __ldg((const float4*)&W[u * 128 + c4]);

    float4 acc = make_float4(0.f, 0.f, 0.f, 0.f);
#pragma unroll 1
    for (int k0 = 0; k0 < DIMX; k0 += 4) {
#pragma unroll
        for (int u = 0; u < 4; u++) {
            const float4 w = wb[u];
            int kn = k0 + 4 + u;
            kn = (kn < DIMX) ? kn : u;               // clamp: keep address valid
            wb[u] = __ldg((const float4*)&W[kn * 128 + c4]);
            const float xv = xr[k0 + u];
            acc.x = fmaf(xv, w.x, acc.x);
            acc.y = fmaf(xv, w.y, acc.y);
            acc.z = fmaf(xv, w.z, acc.z);
            acc.w = fmaf(xv, w.w, acc.w);
        }
    }
    acc.x *= scale; acc.y *= scale; acc.z *= scale; acc.w *= scale;
    *(float4*)&dst[(size_t)(rb + wid) * 128 + c4] = acc;
}

// ---------------------------------------------------------------------------
// Kernel B: FULLY FUSED single pass. grid 1024 (CTA = one query i), block 256
// (8 warps; warp = 128 consecutive j). Lane = (h = lane&7, q = lane>>3).
//
// Per j (all from registers / one stream of loads):
//   pr chunks f = u*4+q  (8 x LDG.128, each 64B contiguous, 8-way h-broadcast)
//   k/v slice (h,q): float4 at row*32 + h*4 + q  (2 x LDG.128, L2-resident)
//   logit partial = (pr . Wb_h)*PAIR_SCALE + q_i . k_j  (lane-local)
//   fold over q-lanes (xor8, xor16) -> p = exp(partial + bb_h) on EVERY lane
//   accp[u] += p * pr[u*4+q]   (16 f32x2 FMA, own chunks -> distinct (h,d))
//   accv    += p * v_slice     (4 FMA)
//   l       += p               (q-duplicated; q==0 lane's value used)
//
// 2-deep rolling prefetch (pr, k, v) -> ~18 KB in flight per SM.
// Epilogue: 8 warps dump 1160-float partials to smem, 256 threads reduce,
// normalize, write out row. No S / P / merge pass at all.
// ---------------------------------------------------------------------------
__global__ void __launch_bounds__(256, 1) fused_kernel(
    const float* __restrict__ pair,
    const float* __restrict__ Wb,
    const float* __restrict__ bb,
    float* __restrict__ out)
{
    __shared__ float mb[8 * 1160];   // 37 KB per-warp partials
    __shared__ float rs[8];          // per-head denom reciprocals

    const int tid  = threadIdx.x;
    const int wid  = tid >> 5;
    const int lane = tid & 31;
    const int h    = lane & 7;
    const int q    = lane >> 3;

    const int i  = blockIdx.x;
    const int j0 = wid * 128;
    const size_t base0 = (size_t)i * NN + j0;

    // Wb rows for this lane's d-set (chunks f = u*4+q), pre-scaled.
    u64 wb2[16];
#pragma unroll
    for (int u = 0; u < 8; u++) {
        const int d = (u * 4 + q) * 4;
        wb2[2 * u]     = pack2(Wb[(d + 0) * 8 + h] * PAIR_SCALE, Wb[(d + 1) * 8 + h] * PAIR_SCALE);
        wb2[2 * u + 1] = pack2(Wb[(d + 2) * 8 + h] * PAIR_SCALE, Wb[(d + 3) * 8 + h] * PAIR_SCALE);
    }
    const float4 qv = *(const float4*)&g_q[(size_t)i * 128 + h * 16 + q * 4];
    const float bbh = bb[h] * PAIR_SCALE;

    const float4* pr4g = (const float4*)pair;
    const float4* k4g  = (const float4*)g_k;
    const float4* v4g  = (const float4*)g_v;
    const int koff = h * 4 + q;      // float4 index of (h,q) slice in a 128-f row

    u64 accp[16];
#pragma unroll
    for (int t = 0; t < 16; t++) accp[t] = 0ull;
    float4 accv = make_float4(0.f, 0.f, 0.f, 0.f);
    float l = 0.0f;

    // 2-deep prefetch stages: N1 = j, N2 = j+1
    float4 prN1[8], prN2[8], kN1, kN2, vN1, vN2;
#pragma unroll
    for (int u = 0; u < 8; u++) prN1[u] = __ldg(pr4g + base0 * 32 + u * 4 + q);
    kN1 = __ldg(k4g + (size_t)j0 * 32 + koff);
    vN1 = __ldg(v4g + (size_t)j0 * 32 + koff);
#pragma unroll
    for (int u = 0; u < 8; u++) prN2[u] = __ldg(pr4g + (base0 + 1) * 32 + u * 4 + q);
    kN2 = __ldg(k4g + (size_t)(j0 + 1) * 32 + koff);
    vN2 = __ldg(v4g + (size_t)(j0 + 1) * 32 + koff);

#pragma unroll 2
    for (int t = 0; t < 128; t++) {
        // consume N1, rotate N2 -> N1, refill N2 at t+2 (clamped)
        float4 prc[8];
#pragma unroll
        for (int u = 0; u < 8; u++) prc[u] = prN1[u];
        const float4 kc = kN1;
        const float4 vc = vN1;
#pragma unroll
        for (int u = 0; u < 8; u++) prN1[u] = prN2[u];
        kN1 = kN2; vN1 = vN2;

        const int tn = (t + 2 < 128) ? (t + 2) : t;     // clamp: valid addr
        const size_t bn = base0 + tn;
#pragma unroll
        for (int u = 0; u < 8; u++) prN2[u] = __ldg(pr4g + bn * 32 + u * 4 + q);
        kN2 = __ldg(k4g + (size_t)(j0 + tn) * 32 + koff);
        vN2 = __ldg(v4g + (size_t)(j0 + tn) * 32 + koff);

        u64 pr2[16];
#pragma unroll
        for (int u = 0; u < 8; u++) {
            pr2[2 * u]     = pack2(prc[u].x, prc[u].y);
            pr2[2 * u + 1] = pack2(prc[u].z, prc[u].w);
        }

        // bias partial: two independent f32x2 chains
        u64 a0 = fmul2(pr2[0], wb2[0]);
        u64 a1 = fmul2(pr2[1], wb2[1]);
#pragma unroll
        for (int u = 1; u < 8; u++) {
            a0 = ffma2(pr2[2 * u],     wb2[2 * u],     a0);
            a1 = ffma2(pr2[2 * u + 1], wb2[2 * u + 1], a1);
        }
        float l0, h0, l1, h1;
        unpack2(a0, l0, h0); unpack2(a1, l1, h1);

        // qk partial for (h, quarter)
        float qk = qv.x * kc.x;
        qk = fmaf(qv.y, kc.y, qk);
        qk = fmaf(qv.z, kc.z, qk);
        qk = fmaf(qv.w, kc.w, qk);

        float dot = ((l0 + h0) + (l1 + h1)) + qk;
        dot += __shfl_xor_sync(0xffffffffu, dot, 8);
        dot += __shfl_xor_sync(0xffffffffu, dot, 16);

        const float p = __expf(dot + bbh);   // identical on all 4 q-lanes of h
        l += p;
        const u64 ph = pack2(p, p);

#pragma unroll
        for (int u = 0; u < 16; u++) accp[u] = ffma2(ph, pr2[u], accp[u]);

        accv.x = fmaf(p, vc.x, accv.x);
        accv.y = fmaf(p, vc.y, accv.y);
        accv.z = fmaf(p, vc.z, accv.z);
        accv.w = fmaf(p, vc.w, accv.w);
    }

    // ---- epilogue: dump per-warp partials, reduce across 8 warps ----
    {
        float* m = mb + wid * 1160;
        *(float4*)&m[koff * 4] = accv;                    // v part: h*16 + q*4
#pragma unroll
        for (int u = 0; u < 8; u++) {
            float a0, a1, a2, a3;
            unpack2(accp[2 * u],     a0, a1);
            unpack2(accp[2 * u + 1], a2, a3);
            *(float4*)&m[128 + h * 128 + u * 16 + q * 4] = make_float4(a0, a1, a2, a3);
        }
        if (q == 0) m[1152 + h] = l;
    }
    __syncthreads();

    // denominators (8 heads) -> reciprocals
    if (tid < 8) {
        float s = 0.0f;
#pragma unroll
        for (int w = 0; w < 8; w++) s += mb[w * 1160 + 1152 + tid];
        rs[tid] = 1.0f / s;
    }
    __syncthreads();

    // reduce 1152 outputs across warps, normalize, store
    const size_t ob = (size_t)i * OUTW;
    for (int idx = tid; idx < OUTW; idx += 256) {
        float s = 0.0f;
#pragma unroll
        for (int w = 0; w < 8; w++) s += mb[w * 1160 + idx];
        const int head = (idx < 128) ? (idx >> 4) : ((idx - 128) >> 7);
        out[ob + idx] = s * rs[head];
    }
}

// ---------------------------------------------------------------------------
extern "C" void kernel_launch(void* const* d_in, const int* in_sizes, int n_in,
                              void* d_out, int out_size)
{
    (void)in_sizes; (void)n_in; (void)out_size;
    const float* x    = (const float*)d_in[0];
    const float* pair = (const float*)d_in[1];
    // d_in[2]=rotations, d_in[3]=translations, d_in[4]=mask: unused by reference math
    const float* Wq = (const float*)d_in[5];
    const float* Wk = (const float*)d_in[6];
    const float* Wv = (const float*)d_in[7];
    const float* Wb = (const float*)d_in[8];
    const float* bb = (const float*)d_in[9];
    float* out = (float*)d_out;

    proj_kernel<<<dim3(128, 3, 1), 256>>>(x, Wq, Wk, Wv);
    fused_kernel<<<1024, 256>>>(pair, Wb, bb, out);
}